// round 10
// baseline (speedup 1.0000x reference)
#include <cuda_runtime.h>

// Single-kernel deterministic reduction for 0.5 * sum((d1-d2)^2).
// R9 structure (fire-and-forget RED epilogue, fixed-point int64 accumulator,
// block-0 finalizer) + deeper unroll (8) in the streaming loop to widen the
// outstanding-LDG window and push DRAM utilization.

#define GRID_BLOCKS 1184
#define BLOCK_THREADS 256
#define FP_SCALE 268435456.0     // 2^28

__device__ unsigned long long g_acc = 0;
__device__ unsigned int g_counter = 0;

__global__ void __launch_bounds__(BLOCK_THREADS)
mse_fused_kernel(const float4* __restrict__ a,
                 const float4* __restrict__ b,
                 int n4,
                 const float* __restrict__ a_s,
                 const float* __restrict__ b_s,
                 int n,
                 float* __restrict__ out)
{
    const int stride = gridDim.x * blockDim.x;
    const int tid = blockIdx.x * blockDim.x + threadIdx.x;

    float acc = 0.0f;

    // Main unrolled stream: batches of 8 grid-stride steps -> up to 16
    // independent float4 LDGs in flight per thread.
    int i = tid;
    const long long total_steps = (n4 - tid + stride - 1) / stride;  // per-thread
    long long full_batches = (tid < n4) ? (total_steps / 8) : 0;

    for (long long bidx = 0; bidx < full_batches; ++bidx) {
        float4 xa[8], xb[8];
        #pragma unroll
        for (int u = 0; u < 8; ++u) {
            xa[u] = __ldcs(a + i + u * stride);
            xb[u] = __ldcs(b + i + u * stride);
        }
        #pragma unroll
        for (int u = 0; u < 8; ++u) {
            float d0 = xa[u].x - xb[u].x;
            float d1 = xa[u].y - xb[u].y;
            float d2 = xa[u].z - xb[u].z;
            float d3 = xa[u].w - xb[u].w;
            acc = fmaf(d0, d0, acc);
            acc = fmaf(d1, d1, acc);
            acc = fmaf(d2, d2, acc);
            acc = fmaf(d3, d3, acc);
        }
        i += 8 * stride;
    }

    // Remainder grid-stride steps (< 8 per thread).
    for (; i < n4; i += stride) {
        float4 x = __ldcs(a + i);
        float4 y = __ldcs(b + i);
        float d0 = x.x - y.x;
        float d1 = x.y - y.y;
        float d2 = x.z - y.z;
        float d3 = x.w - y.w;
        acc = fmaf(d0, d0, acc);
        acc = fmaf(d1, d1, acc);
        acc = fmaf(d2, d2, acc);
        acc = fmaf(d3, d3, acc);
    }

    // Scalar tail (n not multiple of 4): block 0, thread 0 folds it in.
    if (blockIdx.x == 0 && threadIdx.x == 0) {
        for (int t = n4 * 4; t < n; ++t) {
            float d = a_s[t] - b_s[t];
            acc = fmaf(d, d, acc);
        }
    }

    // Block reduce (fixed order -> deterministic block partial)
    #pragma unroll
    for (int o = 16; o > 0; o >>= 1)
        acc += __shfl_down_sync(0xffffffffu, acc, o);

    __shared__ float smem[BLOCK_THREADS / 32];
    const int lane = threadIdx.x & 31;
    const int wid  = threadIdx.x >> 5;
    if (lane == 0) smem[wid] = acc;
    __syncthreads();
    // Warps 1..7 are done after this point — no further block-wide waits.

    if (threadIdx.x == 0) {
        float part = 0.0f;
        #pragma unroll
        for (int w = 0; w < BLOCK_THREADS / 32; ++w)
            part += smem[w];

        // Fixed-point convert (exact via double) -> associative int64 red.
        unsigned long long q =
            (unsigned long long)(long long)llrint((double)part * FP_SCALE);

        // Fire-and-forget: no return value, no stall, no block-retire delay.
        asm volatile("red.relaxed.gpu.global.add.u64 [%0], %1;"
                     :: "l"(&g_acc), "l"(q) : "memory");
        // Release: orders this block's g_acc red before its counter bump.
        asm volatile("red.release.gpu.global.add.u32 [%0], %1;"
                     :: "l"(&g_counter), "r"(1u) : "memory");

        // Block 0 finalizes: spin until all arrivals (incl. our own) land.
        if (blockIdx.x == 0) {
            unsigned int c;
            do {
                asm volatile("ld.acquire.gpu.global.u32 %0, [%1];"
                             : "=r"(c) : "l"(&g_counter) : "memory");
            } while (c != GRID_BLOCKS);
            unsigned long long tot;
            asm volatile("ld.relaxed.gpu.global.u64 %0, [%1];"
                         : "=l"(tot) : "l"(&g_acc) : "memory");
            out[0] = (float)(0.5 * ((double)(long long)tot / FP_SCALE));
            // Reset for next graph replay; kernel boundary publishes these.
            g_acc = 0ull;
            g_counter = 0;
        }
    }
}

extern "C" void kernel_launch(void* const* d_in, const int* in_sizes, int n_in,
                              void* d_out, int out_size)
{
    const float* d1 = (const float*)d_in[0];
    const float* d2 = (const float*)d_in[1];
    float* out = (float*)d_out;

    const int n  = in_sizes[0];   // 40,000,000
    const int n4 = n >> 2;

    mse_fused_kernel<<<GRID_BLOCKS, BLOCK_THREADS>>>(
        (const float4*)d1, (const float4*)d2, n4, d1, d2, n, out);
}

// round 11
// speedup vs baseline: 1.0354x; 1.0354x over previous
#include <cuda_runtime.h>

// Single-kernel deterministic reduction for 0.5 * sum((d1-d2)^2).
// R9 structure (fire-and-forget RED epilogue, fixed-point int64 accumulator,
// block-0 finalizer spin) with streaming loads carrying an L2::256B
// prefetch-size hint: halves DRAM request count on this perfectly-sequential
// two-stream read (neighbor threads consume the co-fetched 128B).

#define GRID_BLOCKS 1184
#define BLOCK_THREADS 256
#define FP_SCALE 268435456.0     // 2^28

__device__ unsigned long long g_acc = 0;
__device__ unsigned int g_counter = 0;

// Streaming float4 load with 256B L2 fetch granularity.
__device__ __forceinline__ float4 ldg_stream256(const float4* p)
{
    float4 v;
    asm("ld.global.L1::evict_first.L2::256B.v4.f32 {%0, %1, %2, %3}, [%4];"
        : "=f"(v.x), "=f"(v.y), "=f"(v.z), "=f"(v.w)
        : "l"(p));
    return v;
}

__global__ void __launch_bounds__(BLOCK_THREADS)
mse_fused_kernel(const float4* __restrict__ a,
                 const float4* __restrict__ b,
                 int n4,
                 const float* __restrict__ a_s,
                 const float* __restrict__ b_s,
                 int n,
                 float* __restrict__ out)
{
    float acc = 0.0f;
    const int stride = gridDim.x * blockDim.x;
    int i = blockIdx.x * blockDim.x + threadIdx.x;

    #pragma unroll 4
    for (; i < n4; i += stride) {
        float4 x = ldg_stream256(a + i);
        float4 y = ldg_stream256(b + i);
        float d0 = x.x - y.x;
        float d1 = x.y - y.y;
        float d2 = x.z - y.z;
        float d3 = x.w - y.w;
        acc = fmaf(d0, d0, acc);
        acc = fmaf(d1, d1, acc);
        acc = fmaf(d2, d2, acc);
        acc = fmaf(d3, d3, acc);
    }

    // Scalar tail (n not multiple of 4): block 0, thread 0 folds it in.
    if (blockIdx.x == 0 && threadIdx.x == 0) {
        for (int t = n4 * 4; t < n; ++t) {
            float d = a_s[t] - b_s[t];
            acc = fmaf(d, d, acc);
        }
    }

    // Block reduce (fixed order -> deterministic block partial)
    #pragma unroll
    for (int o = 16; o > 0; o >>= 1)
        acc += __shfl_down_sync(0xffffffffu, acc, o);

    __shared__ float smem[BLOCK_THREADS / 32];
    const int lane = threadIdx.x & 31;
    const int wid  = threadIdx.x >> 5;
    if (lane == 0) smem[wid] = acc;
    __syncthreads();
    // Warps 1..7 are done after this point — no further block-wide waits.

    if (threadIdx.x == 0) {
        float part = 0.0f;
        #pragma unroll
        for (int w = 0; w < BLOCK_THREADS / 32; ++w)
            part += smem[w];

        // Fixed-point convert (exact via double) -> associative int64 red.
        unsigned long long q =
            (unsigned long long)(long long)llrint((double)part * FP_SCALE);

        // Fire-and-forget: no return value, no stall, no block-retire delay.
        asm volatile("red.relaxed.gpu.global.add.u64 [%0], %1;"
                     :: "l"(&g_acc), "l"(q) : "memory");
        // Release: orders this block's g_acc red before its counter bump.
        asm volatile("red.release.gpu.global.add.u32 [%0], %1;"
                     :: "l"(&g_counter), "r"(1u) : "memory");

        // Block 0 finalizes: spin until all arrivals (incl. our own) land.
        if (blockIdx.x == 0) {
            unsigned int c;
            do {
                asm volatile("ld.acquire.gpu.global.u32 %0, [%1];"
                             : "=r"(c) : "l"(&g_counter) : "memory");
            } while (c != GRID_BLOCKS);
            unsigned long long tot;
            asm volatile("ld.relaxed.gpu.global.u64 %0, [%1];"
                         : "=l"(tot) : "l"(&g_acc) : "memory");
            out[0] = (float)(0.5 * ((double)(long long)tot / FP_SCALE));
            // Reset for next graph replay; kernel boundary publishes these.
            g_acc = 0ull;
            g_counter = 0;
        }
    }
}

extern "C" void kernel_launch(void* const* d_in, const int* in_sizes, int n_in,
                              void* d_out, int out_size)
{
    const float* d1 = (const float*)d_in[0];
    const float* d2 = (const float*)d_in[1];
    float* out = (float*)d_out;

    const int n  = in_sizes[0];   // 40,000,000
    const int n4 = n >> 2;

    mse_fused_kernel<<<GRID_BLOCKS, BLOCK_THREADS>>>(
        (const float4*)d1, (const float4*)d2, n4, d1, d2, n, out);
}